// round 2
// baseline (speedup 1.0000x reference)
#include <cuda_runtime.h>
#include <cuda_bf16.h>

// Problem constants
constexpr int NN = 16384;   // nodes per level
constexpr int DD = 256;     // feature dim
constexpr int KP = 16;      // in-degree
constexpr int LL = 16;      // levels

// Scratch (alloc-free rule: __device__ globals)
__device__ float g_msg[NN * DD];
__device__ float g_z[NN * DD];

// ---------------- Tiled SGEMM with fused bias+relu (+residual) ----------------
// C[i,j] = relu( sum_k A[i,k]*W[k,j] + bias[j] )  (+ res[i,j] if ADD_RES)
// M = NN (16384), N = K = DD (256). BM=BN=64, BK=16, 256 threads, 4x4 per thread.
constexpr int BM = 64, BN = 64, BK = 16;
constexpr int TM = 4,  TN = 4;

template<bool ADD_RES>
__global__ __launch_bounds__(256) void gemm_bias_relu(
    const float* __restrict__ A, const float* __restrict__ W,
    const float* __restrict__ bias, const float* __restrict__ res,
    float* __restrict__ C)
{
    __shared__ float As[BK][BM + 4];   // A transposed tile, padded (keeps 16B align)
    __shared__ float Ws[BK][BN];

    const int bm = blockIdx.y * BM;
    const int bn = blockIdx.x * BN;
    const int tid = threadIdx.x;          // 0..255
    const int tx = tid & 15;              // 16 col-threads
    const int ty = tid >> 4;              // 16 row-threads

    // A-tile load mapping: one float4 per thread. 64 rows x 4 float4 = 256.
    const int arow = tid >> 2;            // 0..63
    const int akv  = tid & 3;             // 0..3 (which float4 along K)
    // W-tile load mapping: 16 rows x 16 float4 = 256.
    const int wrow = tid >> 4;            // 0..15
    const int wcv  = tid & 15;            // 0..15 (which float4 along N)

    float acc[TM][TN] = {};

    for (int k0 = 0; k0 < DD; k0 += BK) {
        float4 av = *reinterpret_cast<const float4*>(
            &A[(size_t)(bm + arow) * DD + k0 + akv * 4]);
        As[akv * 4 + 0][arow] = av.x;
        As[akv * 4 + 1][arow] = av.y;
        As[akv * 4 + 2][arow] = av.z;
        As[akv * 4 + 3][arow] = av.w;

        *reinterpret_cast<float4*>(&Ws[wrow][wcv * 4]) =
            *reinterpret_cast<const float4*>(&W[(size_t)(k0 + wrow) * DD + bn + wcv * 4]);

        __syncthreads();

        #pragma unroll
        for (int kk = 0; kk < BK; kk++) {
            float4 a4 = *reinterpret_cast<const float4*>(&As[kk][ty * TM]);
            float4 b4 = *reinterpret_cast<const float4*>(&Ws[kk][tx * TN]);
            float a[TM] = {a4.x, a4.y, a4.z, a4.w};
            float b[TN] = {b4.x, b4.y, b4.z, b4.w};
            #pragma unroll
            for (int i = 0; i < TM; i++)
                #pragma unroll
                for (int j = 0; j < TN; j++)
                    acc[i][j] = fmaf(a[i], b[j], acc[i][j]);
        }
        __syncthreads();
    }

    #pragma unroll
    for (int i = 0; i < TM; i++) {
        const int row = bm + ty * TM + i;
        #pragma unroll
        for (int j = 0; j < TN; j += 4) {
            const int col = bn + tx * TN + j;
            float4 v;
            v.x = fmaxf(acc[i][j + 0] + bias[col + 0], 0.0f);
            v.y = fmaxf(acc[i][j + 1] + bias[col + 1], 0.0f);
            v.z = fmaxf(acc[i][j + 2] + bias[col + 2], 0.0f);
            v.w = fmaxf(acc[i][j + 3] + bias[col + 3], 0.0f);
            if (ADD_RES) {
                float4 r = *reinterpret_cast<const float4*>(&res[(size_t)row * DD + col]);
                v.x += r.x; v.y += r.y; v.z += r.z; v.w += r.w;
            }
            *reinterpret_cast<float4*>(&C[(size_t)row * DD + col]) = v;
        }
    }
}

// ---------------- Gather + mean over K=16 parents ----------------
// z[i,:] = (1/16) * sum_p msg[idx[i,p], :]
// Block = 256 threads = 4 nodes x 64 threads; each thread owns one float4 chunk.
__global__ __launch_bounds__(256) void gather_mean(
    const float* __restrict__ msg, const int* __restrict__ idx,
    float* __restrict__ z)
{
    const int node = blockIdx.x * 4 + (threadIdx.x >> 6);
    const int c = (threadIdx.x & 63) * 4;
    const int* ip = idx + (size_t)node * KP;

    float4 s = {0.f, 0.f, 0.f, 0.f};
    #pragma unroll
    for (int p = 0; p < KP; p++) {
        const int src = ip[p];
        float4 v = *reinterpret_cast<const float4*>(&msg[(size_t)src * DD + c]);
        s.x += v.x; s.y += v.y; s.z += v.z; s.w += v.w;
    }
    const float inv = 1.0f / (float)KP;
    s.x *= inv; s.y *= inv; s.z *= inv; s.w *= inv;
    *reinterpret_cast<float4*>(&z[(size_t)node * DD + c]) = s;
}

// ---------------- Launch ----------------
extern "C" void kernel_launch(void* const* d_in, const int* in_sizes, int n_in,
                              void* d_out, int out_size)
{
    const float* x   = (const float*)d_in[0];   // [L, N, D]
    const int*   idx = (const int*)  d_in[1];   // [L-1, N, K]
    const float* W1  = (const float*)d_in[2];   // [D, D]
    const float* b1  = (const float*)d_in[3];   // [D]
    const float* W2  = (const float*)d_in[4];   // [D, D]
    const float* b2  = (const float*)d_in[5];   // [D]
    float* out = (float*)d_out;                 // [L, N, D]

    float *msgp = nullptr, *zp = nullptr;
    cudaGetSymbolAddress((void**)&msgp, g_msg);
    cudaGetSymbolAddress((void**)&zp,   g_z);

    const size_t lvl = (size_t)NN * DD;

    // Level 0: passthrough
    cudaMemcpyAsync(out, x, lvl * sizeof(float), cudaMemcpyDeviceToDevice);

    const dim3 ggrid(DD / BN, NN / BM);   // (4, 256)
    const int  gthreads = 256;
    const int  gatherBlocks = NN / 4;     // 4096

    for (int l = 1; l < LL; l++) {
        const float* yprev = out + (size_t)(l - 1) * lvl;
        // msg = relu(yprev @ W1 + b1)
        gemm_bias_relu<false><<<ggrid, gthreads>>>(yprev, W1, b1, nullptr, msgp);
        // z = mean_p msg[idx]
        gather_mean<<<gatherBlocks, 256>>>(msgp, idx + (size_t)(l - 1) * NN * KP, zp);
        // y = relu(z @ W2 + b2) + x[l]
        gemm_bias_relu<true><<<ggrid, gthreads>>>(zp, W2, b2, x + (size_t)l * lvl,
                                                  out + (size_t)l * lvl);
    }
}

// round 4
// speedup vs baseline: 1.6072x; 1.6072x over previous
#include <cuda_runtime.h>
#include <cstdint>

// ---------------- Problem constants ----------------
constexpr int NN = 16384;   // nodes per level
constexpr int DD = 256;     // feature dim
constexpr int KP = 16;      // in-degree
constexpr int LL = 16;      // levels

// ---------------- GEMM tiling ----------------
constexpr int BM = 64, BN = 128, BK = 32;
constexpr int PAD = 36;                    // SMEM row stride in floats (bank-conflict-free)
constexpr int A_FLOATS = BM * PAD;         // 2304 floats per buffer
constexpr int B_FLOATS = BN * PAD;         // 4608 floats per buffer
constexpr int SMEM_BYTES = 2 * (A_FLOATS + B_FLOATS) * 4;  // 55296

// ---------------- Scratch (__device__ globals; alloc-free rule) ----------------
__device__ float g_msg[NN * DD];
__device__ float g_W1t[DD * DD];   // W1^T : Wt[n][k] = W[k][n]
__device__ float g_W2t[DD * DD];

// ---------------- tf32 helpers (portable sm_80+ PTX; no 'a'-features) ----------------
__device__ __forceinline__ uint32_t f2tf(float f) {
    uint32_t r; asm("cvt.rna.tf32.f32 %0, %1;" : "=r"(r) : "f"(f)); return r;
}
__device__ __forceinline__ void mma_tf32(float* c, const uint32_t* a, const uint32_t* b) {
    asm volatile("mma.sync.aligned.m16n8k8.row.col.f32.tf32.tf32.f32 "
                 "{%0,%1,%2,%3}, {%4,%5,%6,%7}, {%8,%9}, {%0,%1,%2,%3};"
                 : "+f"(c[0]), "+f"(c[1]), "+f"(c[2]), "+f"(c[3])
                 : "r"(a[0]), "r"(a[1]), "r"(a[2]), "r"(a[3]), "r"(b[0]), "r"(b[1]));
}

// ---------------- Fused GEMM ----------------
// MODE 0: C = relu(A @ Bt^T + bias)                      (A is activations [NN,DD])
// MODE 1: C = relu(mean_p(A[idx[i,p]]) @ Bt^T + bias) + res   (gather-mean fused into A load)
// Bt is the weight pre-transposed to [n][k] (col-major B for mma row.col).
// Block: 256 threads = 8 warps (2 m x 4 n), warp tile 32x64... -> warp tile 32(m) x 32(n),
// per-warp frags: 2 m-frags (m16) x 4 n-frags (n8), k-chunks of 32 (4 k8 steps), 8 chunks.
template<int MODE, bool ADD_RES>
__global__ __launch_bounds__(256, 2) void gemm_mma(
    const float* __restrict__ A, const int* __restrict__ idx,
    const float* __restrict__ Bt, const float* __restrict__ bias,
    const float* __restrict__ res, float* __restrict__ C)
{
    extern __shared__ float sm[];
    uint32_t* Asu = (uint32_t*)sm;                    // [2][BM][PAD] tf32 bits
    uint32_t* Bsu = (uint32_t*)(sm + 2 * A_FLOATS);   // [2][BN][PAD]

    const int tid = threadIdx.x;
    const int lane = tid & 31, wid = tid >> 5;
    const int g = lane >> 2, t = lane & 3;
    const int wm = (wid & 1) * 32, wn = (wid >> 1) * 32;
    const int bm = blockIdx.y * BM, bn = blockIdx.x * BN;

    const float4* A4 = (const float4*)A;
    const float4* B4 = (const float4*)Bt;

    // MODE1: parent indices for this thread's gather row (4 threads share a row)
    int pr[KP];
    const int grow = tid >> 2;          // 0..63 : row within A tile
    const int gcs = (tid & 3) * 2;      // float4 index pair within 8-float4 chunk row
    if (MODE == 1) {
        const int4* ip = (const int4*)(idx + (size_t)(bm + grow) * KP);
        #pragma unroll
        for (int i = 0; i < 4; i++) {
            int4 v = ip[i];
            pr[i*4+0] = v.x; pr[i*4+1] = v.y; pr[i*4+2] = v.z; pr[i*4+3] = v.w;
        }
    }

    float4 pa[2];          // MODE0 A prefetch
    float4 s0, s1;         // MODE1 gather accumulators
    float4 pb[4];          // B prefetch

    auto prefetchA = [&](int kc) {
        if (MODE == 0) {
            #pragma unroll
            for (int i = 0; i < 2; i++) {
                int e = tid + i * 256, row = e >> 3, v = e & 7;
                pa[i] = A4[(size_t)(bm + row) * 64 + kc * 8 + v];
            }
        } else {
            s0 = make_float4(0.f, 0.f, 0.f, 0.f); s1 = s0;
            #pragma unroll
            for (int p = 0; p < KP; p++) {
                const float4* rp = A4 + (size_t)pr[p] * 64 + kc * 8 + gcs;
                float4 v0 = rp[0], v1 = rp[1];
                s0.x += v0.x; s0.y += v0.y; s0.z += v0.z; s0.w += v0.w;
                s1.x += v1.x; s1.y += v1.y; s1.z += v1.z; s1.w += v1.w;
            }
        }
    };
    auto prefetchB = [&](int kc) {
        #pragma unroll
        for (int i = 0; i < 4; i++) {
            int e = tid + i * 256, n = e >> 3, v = e & 7;
            pb[i] = B4[(size_t)(bn + n) * 64 + kc * 8 + v];
        }
    };
    auto stsAB = [&](int buf) {
        if (MODE == 0) {
            #pragma unroll
            for (int i = 0; i < 2; i++) {
                int e = tid + i * 256, row = e >> 3, v = e & 7;
                uint4 u = {f2tf(pa[i].x), f2tf(pa[i].y), f2tf(pa[i].z), f2tf(pa[i].w)};
                *(uint4*)(Asu + buf * A_FLOATS + row * PAD + v * 4) = u;
            }
        } else {
            const float inv = 1.0f / 16.0f;
            uint4 u0 = {f2tf(s0.x*inv), f2tf(s0.y*inv), f2tf(s0.z*inv), f2tf(s0.w*inv)};
            uint4 u1 = {f2tf(s1.x*inv), f2tf(s1.y*inv), f2tf(s1.z*inv), f2tf(s1.w*inv)};
            uint32_t* p = Asu + buf * A_FLOATS + grow * PAD + gcs * 4;
            *(uint4*)p = u0;
            *(uint4*)(p + 4) = u1;
        }
        #pragma unroll
        for (int i = 0; i < 4; i++) {
            int e = tid + i * 256, n = e >> 3, v = e & 7;
            uint4 u = {f2tf(pb[i].x), f2tf(pb[i].y), f2tf(pb[i].z), f2tf(pb[i].w)};
            *(uint4*)(Bsu + buf * B_FLOATS + n * PAD + v * 4) = u;
        }
    };

    float acc[2][4][4] = {};

    auto compute = [&](int buf) {
        const uint32_t* Ab = Asu + buf * A_FLOATS;
        const uint32_t* Bb = Bsu + buf * B_FLOATS;
        #pragma unroll
        for (int ks = 0; ks < 4; ks++) {
            const int k0 = ks * 8;
            uint32_t a[2][4], b[4][2];
            #pragma unroll
            for (int mf = 0; mf < 2; mf++) {
                const uint32_t* r0 = Ab + (wm + mf*16 + g) * PAD + k0 + t;
                const uint32_t* r1 = Ab + (wm + mf*16 + 8 + g) * PAD + k0 + t;
                a[mf][0] = r0[0]; a[mf][1] = r1[0]; a[mf][2] = r0[4]; a[mf][3] = r1[4];
            }
            #pragma unroll
            for (int nf = 0; nf < 4; nf++) {
                const uint32_t* rb = Bb + (wn + nf*8 + g) * PAD + k0 + t;
                b[nf][0] = rb[0]; b[nf][1] = rb[4];
            }
            #pragma unroll
            for (int mf = 0; mf < 2; mf++)
                #pragma unroll
                for (int nf = 0; nf < 4; nf++)
                    mma_tf32(acc[mf][nf], a[mf], b[nf]);
        }
    };

    // Software pipeline: reg-prefetch next chunk while computing current.
    prefetchA(0); prefetchB(0);
    stsAB(0);
    __syncthreads();
    #pragma unroll
    for (int kc = 0; kc < DD / BK; kc++) {
        if (kc < DD / BK - 1) { prefetchA(kc + 1); prefetchB(kc + 1); }
        compute(kc & 1);
        if (kc < DD / BK - 1) { stsAB((kc + 1) & 1); __syncthreads(); }
    }

    // Epilogue: bias + relu (+ residual)
    #pragma unroll
    for (int mf = 0; mf < 2; mf++) {
        const int r0 = bm + wm + mf*16 + g;
        #pragma unroll
        for (int nf = 0; nf < 4; nf++) {
            const int col = bn + wn + nf*8 + 2*t;
            float2 bb = *(const float2*)(bias + col);
            float2 v0, v1;
            v0.x = fmaxf(acc[mf][nf][0] + bb.x, 0.f);
            v0.y = fmaxf(acc[mf][nf][1] + bb.y, 0.f);
            v1.x = fmaxf(acc[mf][nf][2] + bb.x, 0.f);
            v1.y = fmaxf(acc[mf][nf][3] + bb.y, 0.f);
            if (ADD_RES) {
                float2 q0 = *(const float2*)(res + (size_t)r0 * DD + col);
                float2 q1 = *(const float2*)(res + (size_t)(r0 + 8) * DD + col);
                v0.x += q0.x; v0.y += q0.y; v1.x += q1.x; v1.y += q1.y;
            }
            *(float2*)(C + (size_t)r0 * DD + col) = v0;
            *(float2*)(C + (size_t)(r0 + 8) * DD + col) = v1;
        }
    }
}

// ---------------- 256x256 transpose (weights -> N-major B operand) ----------------
__global__ void transpose256(const float* __restrict__ W, float* __restrict__ Wt) {
    __shared__ float tbuf[32][33];
    const int bx = (blockIdx.x & 7) * 32;
    const int by = (blockIdx.x >> 3) * 32;
    const int x = threadIdx.x, y = threadIdx.y;
    #pragma unroll
    for (int i = 0; i < 32; i += 8)
        tbuf[y + i][x] = W[(by + y + i) * DD + bx + x];
    __syncthreads();
    #pragma unroll
    for (int i = 0; i < 32; i += 8)
        Wt[(bx + y + i) * DD + by + x] = tbuf[x][y + i];
}

// ---------------- Launch ----------------
extern "C" void kernel_launch(void* const* d_in, const int* in_sizes, int n_in,
                              void* d_out, int out_size)
{
    const float* x   = (const float*)d_in[0];   // [L, N, D]
    const int*   idx = (const int*)  d_in[1];   // [L-1, N, K]
    const float* W1  = (const float*)d_in[2];   // [D, D]
    const float* b1  = (const float*)d_in[3];   // [D]
    const float* W2  = (const float*)d_in[4];   // [D, D]
    const float* b2  = (const float*)d_in[5];   // [D]
    float* out = (float*)d_out;                 // [L, N, D]

    float *msgp, *w1t, *w2t;
    cudaGetSymbolAddress((void**)&msgp, g_msg);
    cudaGetSymbolAddress((void**)&w1t,  g_W1t);
    cudaGetSymbolAddress((void**)&w2t,  g_W2t);

    cudaFuncSetAttribute(gemm_mma<0, false>, cudaFuncAttributeMaxDynamicSharedMemorySize, SMEM_BYTES);
    cudaFuncSetAttribute(gemm_mma<1, true>,  cudaFuncAttributeMaxDynamicSharedMemorySize, SMEM_BYTES);

    const size_t lvl = (size_t)NN * DD;

    // Pre-transpose weights (B operand is col-major [n][k] for mma row.col)
    transpose256<<<64, dim3(32, 8)>>>(W1, w1t);
    transpose256<<<64, dim3(32, 8)>>>(W2, w2t);

    // Level 0: passthrough
    cudaMemcpyAsync(out, x, lvl * sizeof(float), cudaMemcpyDeviceToDevice);

    const dim3 grid(DD / BN, NN / BM);   // (2, 256)

    for (int l = 1; l < LL; l++) {
        const float* yprev = out + (size_t)(l - 1) * lvl;
        // msg = relu(yprev @ W1 + b1)
        gemm_mma<0, false><<<grid, 256, SMEM_BYTES>>>(yprev, nullptr, w1t, b1, nullptr, msgp);
        // y = relu(mean_p msg[idx] @ W2 + b2) + x[l]   (gather fused into A-load)
        gemm_mma<1, true><<<grid, 256, SMEM_BYTES>>>(msgp, idx + (size_t)(l - 1) * NN * KP,
                                                     w2t, b2, x + (size_t)l * lvl,
                                                     out + (size_t)l * lvl);
    }
}